// round 1
// baseline (speedup 1.0000x reference)
#include <cuda_runtime.h>
#include <cuda_bf16.h>
#include <math.h>

// ============================================================================
// DCGRU cell, fp32 SIMT implementation.
//
// Layouts:
//   X buffers: [N rows][B*C cols] i.e. element (n,b,c) at n*2112 + b*66 + c
//              equivalently row r = n*32+b, X[r*66+c].
//   Diffusion step = GEMM  Y[2048,2112] = S[2048,2048] @ X[2048,2112]
//   Dense step     = Z[65536,OUT] = sum_m X_m[65536,66] @ W_m[66,OUT]
//                    where W_m[c][o] = W[(c*5+m)*OUT + o]
// ============================================================================

#define NNODE 2048
#define BATCH 32
#define UNITS 64
#define CDIM  66
#define NCOLS (BATCH * CDIM)   // 2112
#define ROWS  (NNODE * BATCH)  // 65536
#define HXLEN (NNODE * UNITS)  // 131072

// Scratch (device globals: allocation-free)
__device__ float g_X0A[ROWS * CDIM];
__device__ float g_X0B[ROWS * CDIM];
__device__ float g_X1A[ROWS * CDIM];
__device__ float g_X2A[ROWS * CDIM];
__device__ float g_X1B[ROWS * CDIM];
__device__ float g_X2B[ROWS * CDIM];
__device__ float g_U  [ROWS * UNITS];

// ----------------------------------------------------------------------------
// build_x0: X0A[(n*32+b)*66 + c] = c<2 ? inputs[b][n*2+c] : hx[b][n*64+(c-2)]
// Also seeds the input columns (c<2) of X0B (its hx part comes from the
// ru epilogue later).
// ----------------------------------------------------------------------------
__global__ void build_x0_kernel(const float* __restrict__ inputs,
                                const float* __restrict__ hx,
                                float* __restrict__ X0A,
                                float* __restrict__ X0B)
{
    int idx = blockIdx.x * blockDim.x + threadIdx.x;
    if (idx >= ROWS * CDIM) return;
    int r = idx / CDIM;
    int c = idx - r * CDIM;
    int n = r >> 5;        // r = n*32 + b
    int b = r & 31;
    float v;
    if (c < 2) {
        v = inputs[b * (NNODE * 2) + n * 2 + c];
        X0B[idx] = v;
    } else {
        v = hx[b * HXLEN + n * UNITS + (c - 2)];
    }
    X0A[idx] = v;
}

// ----------------------------------------------------------------------------
// sgemm_diff: Y = S @ X              (mode 0)
//             Y = 2*(S @ X) - Xsub   (mode 1)
// M=K=2048, NC=2112. 128x128x8 tiles, double-buffered smem, 8x8 per thread.
// ----------------------------------------------------------------------------
__global__ __launch_bounds__(256, 2)
void sgemm_diff_kernel(const float* __restrict__ S,
                       const float* __restrict__ X,
                       const float* __restrict__ Xsub,
                       float* __restrict__ Y,
                       int mode)
{
    const int K = 2048;
    const int NC = 2112;

    __shared__ float As[2][8][128];
    __shared__ float Bs[2][8][132];   // padded row (132 floats, 16B-aligned rows)

    int tid = threadIdx.x;
    int tx = tid & 15;
    int ty = tid >> 4;

    int rowBase = blockIdx.y * 128;
    int colBase = blockIdx.x * 128;

    // A-load mapping: 128 rows x 8 k, 2 float4 per row
    int aRow = tid >> 1;          // 0..127
    int aK   = (tid & 1) * 4;     // 0 or 4
    // B-load mapping: 8 k x 128 cols, 1 float4 per thread
    int bK   = tid >> 5;          // 0..7
    int bCol = (tid & 31) * 4;    // 0..124
    bool bPred = (colBase + bCol) < NC;

    const float* Ag = S + (size_t)(rowBase + aRow) * K + aK;
    const float* Bg = X + (size_t)bK * NC + colBase + bCol;

    float4 aReg, bReg;
    float4 z4; z4.x = z4.y = z4.z = z4.w = 0.f;

    // preload tile 0
    aReg = *(const float4*)(Ag);
    bReg = bPred ? *(const float4*)(Bg) : z4;
    As[0][aK + 0][aRow] = aReg.x;
    As[0][aK + 1][aRow] = aReg.y;
    As[0][aK + 2][aRow] = aReg.z;
    As[0][aK + 3][aRow] = aReg.w;
    *(float4*)&Bs[0][bK][bCol] = bReg;
    __syncthreads();

    float acc[8][8];
#pragma unroll
    for (int i = 0; i < 8; i++)
#pragma unroll
        for (int j = 0; j < 8; j++) acc[i][j] = 0.f;

    int buf = 0;
    for (int k0 = 8; k0 <= K; k0 += 8) {
        bool hasNext = (k0 < K);
        if (hasNext) {
            aReg = *(const float4*)(Ag + k0);
            bReg = bPred ? *(const float4*)(Bg + (size_t)k0 * NC) : z4;
        }

#pragma unroll
        for (int kk = 0; kk < 8; kk++) {
            float4 t0 = *(const float4*)&As[buf][kk][ty * 4];
            float4 t1 = *(const float4*)&As[buf][kk][64 + ty * 4];
            float4 s0 = *(const float4*)&Bs[buf][kk][tx * 4];
            float4 s1 = *(const float4*)&Bs[buf][kk][64 + tx * 4];
            float a[8] = {t0.x, t0.y, t0.z, t0.w, t1.x, t1.y, t1.z, t1.w};
            float b[8] = {s0.x, s0.y, s0.z, s0.w, s1.x, s1.y, s1.z, s1.w};
#pragma unroll
            for (int i = 0; i < 8; i++)
#pragma unroll
                for (int j = 0; j < 8; j++)
                    acc[i][j] = fmaf(a[i], b[j], acc[i][j]);
        }

        if (hasNext) {
            int nb = buf ^ 1;
            As[nb][aK + 0][aRow] = aReg.x;
            As[nb][aK + 1][aRow] = aReg.y;
            As[nb][aK + 2][aRow] = aReg.z;
            As[nb][aK + 3][aRow] = aReg.w;
            *(float4*)&Bs[nb][bK][bCol] = bReg;
            __syncthreads();
            buf = nb;
        }
    }

    // epilogue
#pragma unroll
    for (int i = 0; i < 8; i++) {
        int r = rowBase + ((i < 4) ? (ty * 4 + i) : (64 + ty * 4 + (i - 4)));
#pragma unroll
        for (int j = 0; j < 8; j++) {
            int c = colBase + ((j < 4) ? (tx * 4 + j) : (64 + tx * 4 + (j - 4)));
            if (c < NC) {
                float v = acc[i][j];
                if (mode) v = 2.f * v - Xsub[(size_t)r * NC + c];
                Y[(size_t)r * NC + c] = v;
            }
        }
    }
}

// ----------------------------------------------------------------------------
// dense_gconv<OUT>: Z[r][o] = bias[o] + sum_m sum_c Xm[r][c] * W[(c*5+m)*OUT+o]
// OUT=128: sigmoid epilogue -> r*hx into X0B (c>=2 slots) and u into g_U
// OUT=64 : tanh epilogue -> new_state into d_out
// Block = 128 rows x OUT cols, 256 threads.
// ----------------------------------------------------------------------------
template <int OUT>
__global__ __launch_bounds__(256, 2)
void dense_gconv_kernel(const float* __restrict__ Xm0,
                        const float* __restrict__ Xm1,
                        const float* __restrict__ Xm2,
                        const float* __restrict__ Xm3,
                        const float* __restrict__ Xm4,
                        const float* __restrict__ W,
                        const float* __restrict__ bias,
                        const float* __restrict__ hx,
                        float* __restrict__ u_buf,
                        float* __restrict__ X0b,
                        float* __restrict__ out)
{
    constexpr int JF = (OUT == 128) ? 8 : 4;

    __shared__ float Xs[33][132];   // [c][row], padded
    __shared__ float Ws[33][OUT];   // [c][o]

    int tid = threadIdx.x;
    int tx = tid & 15;
    int ty = tid >> 4;
    int r0 = blockIdx.x * 128;

    float acc[8][JF];
#pragma unroll
    for (int i = 0; i < 8; i++)
#pragma unroll
        for (int j = 0; j < JF; j++) acc[i][j] = 0.f;

    const float* Xp[5] = {Xm0, Xm1, Xm2, Xm3, Xm4};

    for (int m = 0; m < 5; m++) {
        const float* Xb = Xp[m];
        for (int half = 0; half < 2; half++) {
            int c0 = half * 33;
            __syncthreads();   // protect previous tile reads
            // load X tile (128 rows x 33 c), stored transposed
            for (int i = tid; i < 128 * 33; i += 256) {
                int row = i / 33;
                int c = i - row * 33;
                Xs[c][row] = Xb[(size_t)(r0 + row) * CDIM + c0 + c];
            }
            // load W tile (33 c x OUT)
            for (int i = tid; i < 33 * OUT; i += 256) {
                int c = i / OUT;
                int o = i - c * OUT;
                Ws[c][o] = W[(size_t)((c0 + c) * 5 + m) * OUT + o];
            }
            __syncthreads();

            for (int c = 0; c < 33; c++) {
                float a[8];
#pragma unroll
                for (int i = 0; i < 4; i++) {
                    a[i]     = Xs[c][ty * 4 + i];
                    a[i + 4] = Xs[c][64 + ty * 4 + i];
                }
                float b[JF];
#pragma unroll
                for (int j = 0; j < 4; j++) b[j] = Ws[c][tx * 4 + j];
                if (OUT == 128) {
#pragma unroll
                    for (int j = 0; j < 4; j++) b[j + 4] = Ws[c][64 + tx * 4 + j];
                }
#pragma unroll
                for (int i = 0; i < 8; i++)
#pragma unroll
                    for (int j = 0; j < JF; j++)
                        acc[i][j] = fmaf(a[i], b[j], acc[i][j]);
            }
        }
    }

    // epilogue
#pragma unroll
    for (int i = 0; i < 8; i++) {
        int r = r0 + ((i < 4) ? (ty * 4 + i) : (64 + ty * 4 + (i - 4)));
        int n = r >> 5;
        int b = r & 31;
#pragma unroll
        for (int j = 0; j < JF; j++) {
            int o = (OUT == 128)
                        ? ((j < 4) ? (tx * 4 + j) : (64 + tx * 4 + (j - 4)))
                        : (tx * 4 + j);
            float z = acc[i][j] + bias[o];
            if (OUT == 128) {
                float s = 1.f / (1.f + expf(-z));
                if (o < UNITS) {
                    // r-gate: write r*hx into second-gconv X0 (hx slot c = 2+o)
                    float h = hx[(size_t)b * HXLEN + n * UNITS + o];
                    X0b[(size_t)r * CDIM + 2 + o] = s * h;
                } else {
                    u_buf[(size_t)r * UNITS + (o - UNITS)] = s;
                }
            } else {
                float cc = tanhf(z);
                float uu = u_buf[(size_t)r * UNITS + o];
                float h = hx[(size_t)b * HXLEN + n * UNITS + o];
                out[(size_t)b * HXLEN + n * UNITS + o] = uu * h + (1.f - uu) * cc;
            }
        }
    }
}

// ----------------------------------------------------------------------------
// launch
// ----------------------------------------------------------------------------
extern "C" void kernel_launch(void* const* d_in, const int* in_sizes, int n_in,
                              void* d_out, int out_size)
{
    const float* inputs = (const float*)d_in[0];
    const float* hx     = (const float*)d_in[1];
    const float* S0     = (const float*)d_in[2];
    const float* S1     = (const float*)d_in[3];
    const float* Wru    = (const float*)d_in[4];
    const float* bru    = (const float*)d_in[5];
    const float* Wc     = (const float*)d_in[6];
    const float* bc     = (const float*)d_in[7];
    float* out = (float*)d_out;

    float *X0A, *X0B, *X1A, *X2A, *X1B, *X2B, *U;
    cudaGetSymbolAddress((void**)&X0A, g_X0A);
    cudaGetSymbolAddress((void**)&X0B, g_X0B);
    cudaGetSymbolAddress((void**)&X1A, g_X1A);
    cudaGetSymbolAddress((void**)&X2A, g_X2A);
    cudaGetSymbolAddress((void**)&X1B, g_X1B);
    cudaGetSymbolAddress((void**)&X2B, g_X2B);
    cudaGetSymbolAddress((void**)&U,   g_U);

    dim3 gemmGrid(17, 16);   // col blocks x row blocks (2112/128 -> 17, 2048/128 -> 16)
    dim3 gemmBlk(256);
    int buildBlocks = (ROWS * CDIM + 255) / 256;
    dim3 denseGrid(ROWS / 128);

    // ---- gconv 1 (state = hx) ----
    build_x0_kernel<<<buildBlocks, 256>>>(inputs, hx, X0A, X0B);

    sgemm_diff_kernel<<<gemmGrid, gemmBlk>>>(S0, X0A, nullptr, X1A, 0);
    sgemm_diff_kernel<<<gemmGrid, gemmBlk>>>(S0, X1A, X0A,     X2A, 1);
    sgemm_diff_kernel<<<gemmGrid, gemmBlk>>>(S1, X0A, nullptr, X1B, 0);
    sgemm_diff_kernel<<<gemmGrid, gemmBlk>>>(S1, X1B, X0A,     X2B, 1);

    // sigmoid gates; writes r*hx into X0B and u into g_U
    dense_gconv_kernel<128><<<denseGrid, 256>>>(X0A, X1A, X2A, X1B, X2B,
                                                Wru, bru, hx, U, X0B, nullptr);

    // ---- gconv 2 (state = r*hx) ----
    sgemm_diff_kernel<<<gemmGrid, gemmBlk>>>(S0, X0B, nullptr, X1A, 0);
    sgemm_diff_kernel<<<gemmGrid, gemmBlk>>>(S0, X1A, X0B,     X2A, 1);
    sgemm_diff_kernel<<<gemmGrid, gemmBlk>>>(S1, X0B, nullptr, X1B, 0);
    sgemm_diff_kernel<<<gemmGrid, gemmBlk>>>(S1, X1B, X0B,     X2B, 1);

    // tanh + final combine, writes d_out
    dense_gconv_kernel<64><<<denseGrid, 256>>>(X0B, X1A, X2A, X1B, X2B,
                                               Wc, bc, hx, U, nullptr, out);
}

// round 5
// speedup vs baseline: 2.4890x; 2.4890x over previous
#include <cuda_runtime.h>
#include <cstdint>
#include <math.h>

// ============================================================================
// DCGRU cell — mma.sync TF32 diffusion GEMMs (sm_80-class PTX, legal on the
// harness's compute_100/sm_100 target) + fp32 SIMT dense gconvs.
// Static shared memory only; no dyn-smem attr, no mbarriers, no spin waits.
//
// All X buffers stored TRANSPOSED: Xt[col][node], col = b*66+c (padded to 2176)
// Diffusion GEMM: Yt[n][m] = sum_k S[m][k] * Xt[n][k]   (m16n8k8.row.col)
// ============================================================================

#define NNODE 2048
#define BATCH 32
#define UNITS 64
#define CDIM  66
#define NC    2112            // BATCH*CDIM
#define NCP   2176            // padded to 17*128
#define ROWS  65536           // NNODE*BATCH
#define HXLEN 131072          // NNODE*UNITS

// Scratch (device globals, allocation-free)
__device__ float g_X0A[(size_t)NCP * NNODE];
__device__ float g_X0B[(size_t)NCP * NNODE];
__device__ float g_X1A[(size_t)NCP * NNODE];
__device__ float g_X2A[(size_t)NCP * NNODE];
__device__ float g_X1B[(size_t)NCP * NNODE];
__device__ float g_X2B[(size_t)NCP * NNODE];
__device__ float g_U  [(size_t)UNITS * ROWS];   // u_t[o][b*2048+n]

// ---------------------------------------------------------------------------
// helpers
// ---------------------------------------------------------------------------
__device__ __forceinline__ uint32_t smem_u32(const void* p) {
    uint32_t a;
    asm("{ .reg .u64 t; cvta.to.shared.u64 t, %1; cvt.u32.u64 %0, t; }"
        : "=r"(a) : "l"(p));
    return a;
}
__device__ __forceinline__ void cp_async16(uint32_t dst, const void* src) {
    asm volatile("cp.async.cg.shared.global [%0], [%1], 16;"
                 :: "r"(dst), "l"(src) : "memory");
}
#define CP_COMMIT() asm volatile("cp.async.commit_group;" ::: "memory")
#define CP_WAIT(n)  asm volatile("cp.async.wait_group %0;" :: "n"(n) : "memory")

// m16n8k8 tf32 mma, D+=A*B (fp32 bits as tf32 operands; HW truncates mantissa)
__device__ __forceinline__ void mma_tf32(float* c, const uint32_t* a,
                                         uint32_t b0, uint32_t b1) {
    asm volatile(
        "mma.sync.aligned.m16n8k8.row.col.f32.tf32.tf32.f32 "
        "{%0,%1,%2,%3}, {%4,%5,%6,%7}, {%8,%9}, {%0,%1,%2,%3};"
        : "+f"(c[0]), "+f"(c[1]), "+f"(c[2]), "+f"(c[3])
        : "r"(a[0]), "r"(a[1]), "r"(a[2]), "r"(a[3]), "r"(b0), "r"(b1));
}

// ---------------------------------------------------------------------------
// build_x0: fill transposed X0A (and input cols + pads of X0B)
// ---------------------------------------------------------------------------
__global__ void build_x0_kernel(const float* __restrict__ inputs,
                                const float* __restrict__ hx,
                                float* __restrict__ X0A,
                                float* __restrict__ X0B)
{
    size_t idx = (size_t)blockIdx.x * 256 + threadIdx.x;
    if (idx >= (size_t)NCP * NNODE) return;
    int col = (int)(idx >> 11);
    int n = (int)(idx & 2047);
    if (col >= NC) { X0A[idx] = 0.f; X0B[idx] = 0.f; return; }
    int b = col / CDIM;
    int c = col - b * CDIM;
    float v;
    if (c < 2) {
        v = inputs[b * (NNODE * 2) + n * 2 + c];
        X0B[idx] = v;
    } else {
        v = hx[(size_t)b * HXLEN + n * UNITS + (c - 2)];
    }
    X0A[idx] = v;
}

// ---------------------------------------------------------------------------
// tc_gemm (mma.sync tf32): Yt = S @ Xt (mode 0) / Yt = 2*(S@Xt) - XsubT (mode 1)
// grid (17 colTiles, 16 rowTiles), 256 threads, 40 KB static smem.
// smem tiles: [128 rows][16 k] stride 20 floats, double buffered.
// Warp grid 4m x 2n; warp tile 32(m) x 64(n); fragments m16n8k8.
// SB layout (floats): A0=0, A1=2560, B0=5120, B1=7680. Epilogue reuses SB.
// ---------------------------------------------------------------------------
__device__ __forceinline__ void load_tile16(uint32_t dstB, const float* src,
                                            int k0, int tid)
{
#pragma unroll
    for (int i = 0; i < 2; i++) {
        int id = tid + i * 256;
        int r = id >> 2;          // 0..127
        int q = id & 3;           // float4 index in 16-k row
        cp_async16(dstB + (uint32_t)(r * 20 + q * 4) * 4,
                   src + (size_t)r * NNODE + k0 + q * 4);
    }
}

__global__ __launch_bounds__(256)
void tc_gemm_kernel(const float* __restrict__ S,
                    const float* __restrict__ Xt,
                    const float* __restrict__ XsubT,
                    float* __restrict__ Yt,
                    int mode)
{
    __shared__ float SB[10240];   // 40 KB
    uint32_t smB = smem_u32(SB);

    int tid = threadIdx.x;
    int lane = tid & 31;
    int w = tid >> 5;
    int wm = (w & 3) * 32;     // warp m offset
    int wn = (w >> 2) * 64;    // warp n offset
    int mr = lane >> 2;        // groupID 0..7
    int kc = lane & 3;         // threadID_in_group 0..3

    int rowBase = blockIdx.y * 128;   // m (output node)
    int colBase = blockIdx.x * 128;   // n (X col)

    const float* Ag = S  + (size_t)rowBase * NNODE;
    const float* Bg = Xt + (size_t)colBase * NNODE;

    float acc[2][8][4];
#pragma unroll
    for (int f = 0; f < 2; f++)
#pragma unroll
        for (int g = 0; g < 8; g++)
#pragma unroll
            for (int v = 0; v < 4; v++) acc[f][g][v] = 0.f;

    // preload k-tile 0 -> buf0
    load_tile16(smB, Ag, 0, tid);
    load_tile16(smB + 5120 * 4, Bg, 0, tid);
    CP_COMMIT();

    for (int kt = 0; kt < 128; ++kt) {
        int p = kt & 1;
        if (kt + 1 < 128) {
            load_tile16(smB + (uint32_t)((p ^ 1) * 2560) * 4, Ag, (kt + 1) * 16, tid);
            load_tile16(smB + (uint32_t)(5120 + (p ^ 1) * 2560) * 4, Bg, (kt + 1) * 16, tid);
            CP_COMMIT();
            CP_WAIT(1);
        } else {
            CP_WAIT(0);
        }
        __syncthreads();

        const float* As = SB + p * 2560;
        const float* Bs = SB + 5120 + p * 2560;

#pragma unroll
        for (int ks = 0; ks < 2; ks++) {
            int kk = ks * 8;
            uint32_t a[2][4];
#pragma unroll
            for (int f = 0; f < 2; f++) {
                int m0 = wm + f * 16 + mr;
                a[f][0] = __float_as_uint(As[m0 * 20 + kk + kc]);
                a[f][1] = __float_as_uint(As[(m0 + 8) * 20 + kk + kc]);
                a[f][2] = __float_as_uint(As[m0 * 20 + kk + kc + 4]);
                a[f][3] = __float_as_uint(As[(m0 + 8) * 20 + kk + kc + 4]);
            }
#pragma unroll
            for (int g = 0; g < 8; g++) {
                int nb = wn + g * 8 + mr;
                uint32_t b0 = __float_as_uint(Bs[nb * 20 + kk + kc]);
                uint32_t b1 = __float_as_uint(Bs[nb * 20 + kk + kc + 4]);
                mma_tf32(acc[0][g], a[0], b0, b1);
                mma_tf32(acc[1][g], a[1], b0, b1);
            }
        }
        __syncthreads();   // before next load overwrites buf p
    }

    // ---- epilogue: transpose in 32-n chunks through SB, coalesced stores ----
    // Cs chunk: [32 n][132 m-stride]; 4224 floats, fits in SB.
    float* Cs = SB;
    for (int cc = 0; cc < 4; cc++) {
        __syncthreads();
        if ((wn == 0) == (cc < 2)) {      // wn=0 warps own chunks 0,1; wn=64 -> 2,3
            int gbase = (cc & 1) * 4;
#pragma unroll
            for (int g2 = 0; g2 < 4; g2++) {
                int g = gbase + g2;
                int jn = g * 8 - (cc & 1) * 32 + 2 * kc;   // 0..30
#pragma unroll
                for (int f = 0; f < 2; f++) {
                    int i0 = wm + f * 16 + mr;
                    Cs[jn * 132 + i0]           = acc[f][g][0];
                    Cs[(jn + 1) * 132 + i0]     = acc[f][g][1];
                    Cs[jn * 132 + i0 + 8]       = acc[f][g][2];
                    Cs[(jn + 1) * 132 + i0 + 8] = acc[f][g][3];
                }
            }
        }
        __syncthreads();
#pragma unroll
        for (int i = 0; i < 4; i++) {
            int u = tid + i * 256;
            int n = u >> 5;            // 0..31
            int mq = u & 31;           // float4 index within 128 m
            float4 v = *(const float4*)&Cs[n * 132 + mq * 4];
            size_t off = (size_t)(colBase + cc * 32 + n) * NNODE + rowBase + mq * 4;
            if (mode) {
                float4 xs = *(const float4*)&XsubT[off];
                v.x = 2.f * v.x - xs.x;
                v.y = 2.f * v.y - xs.y;
                v.z = 2.f * v.z - xs.z;
                v.w = 2.f * v.w - xs.w;
            }
            *(float4*)&Yt[off] = v;
        }
    }
}

// ---------------------------------------------------------------------------
// dense_gconv<OUT>: Z[(b,n)][o] = bias[o] + sum_m sum_c Xt_m[b*66+c][n]*W[(c*5+m)*OUT+o]
// grid (16 nTiles, 32 b), 256 threads. tx -> n (rows), ty -> o (cols).
// OUT=128: sigmoid; o<64 -> r*hx into X0Bt, o>=64 -> u into u_t
// OUT=64 : tanh; final new_state into out (original layout)
// ---------------------------------------------------------------------------
__device__ __forceinline__ float sigf(float x) { return 1.f / (1.f + expf(-x)); }

template <int OUT>
__global__ __launch_bounds__(256)
void dense_gconv_kernel(const float* __restrict__ Xm0,
                        const float* __restrict__ Xm1,
                        const float* __restrict__ Xm2,
                        const float* __restrict__ Xm3,
                        const float* __restrict__ Xm4,
                        const float* __restrict__ W,
                        const float* __restrict__ bias,
                        const float* __restrict__ hx,
                        float* __restrict__ u_t,
                        float* __restrict__ X0b_t,
                        float* __restrict__ out)
{
    constexpr int JF = (OUT == 128) ? 8 : 4;

    __shared__ float Xs[33][128];
    __shared__ float Ws[33][OUT];

    int tid = threadIdx.x;
    int tx = tid & 15;    // n groups
    int ty = tid >> 4;    // o groups
    int n0 = blockIdx.x * 128;
    int b  = blockIdx.y;

    float acc[8][JF];
#pragma unroll
    for (int i = 0; i < 8; i++)
#pragma unroll
        for (int j = 0; j < JF; j++) acc[i][j] = 0.f;

    const float* Xp[5] = {Xm0, Xm1, Xm2, Xm3, Xm4};

#pragma unroll
    for (int mm = 0; mm < 5; mm++) {
        const float* Xb = Xp[mm];
        for (int half = 0; half < 2; half++) {
            int c0 = half * 33;
            __syncthreads();
            for (int i4 = tid; i4 < 33 * 32; i4 += 256) {
                int c = i4 >> 5;
                int n4 = i4 & 31;
                *(float4*)&Xs[c][n4 * 4] =
                    *(const float4*)&Xb[(size_t)(b * CDIM + c0 + c) * NNODE + n0 + n4 * 4];
            }
            for (int i4 = tid; i4 < 33 * (OUT / 4); i4 += 256) {
                int c = i4 / (OUT / 4);
                int o4 = i4 - c * (OUT / 4);
                *(float4*)&Ws[c][o4 * 4] =
                    *(const float4*)&W[(size_t)((c0 + c) * 5 + mm) * OUT + o4 * 4];
            }
            __syncthreads();

            for (int c = 0; c < 33; c++) {
                float4 a0 = *(const float4*)&Xs[c][tx * 4];
                float4 a1 = *(const float4*)&Xs[c][64 + tx * 4];
                float a[8] = {a0.x, a0.y, a0.z, a0.w, a1.x, a1.y, a1.z, a1.w};
                float4 w0 = *(const float4*)&Ws[c][ty * 4];
                float bb[JF];
                bb[0] = w0.x; bb[1] = w0.y; bb[2] = w0.z; bb[3] = w0.w;
                if (OUT == 128) {
                    float4 w1 = *(const float4*)&Ws[c][64 + ty * 4];
                    bb[4] = w1.x; bb[5] = w1.y; bb[6] = w1.z; bb[7] = w1.w;
                }
#pragma unroll
                for (int i = 0; i < 8; i++)
#pragma unroll
                    for (int j = 0; j < JF; j++)
                        acc[i][j] = fmaf(a[i], bb[j], acc[i][j]);
            }
        }
    }

    // ---- epilogue ----
    if (OUT == 128) {
        float br[4], bu[4];
#pragma unroll
        for (int j = 0; j < 4; j++) { br[j] = bias[ty * 4 + j]; bu[j] = bias[64 + ty * 4 + j]; }
#pragma unroll
        for (int g = 0; g < 2; g++) {
            int bn = n0 + g * 64 + tx * 4;
            float4 h[4];
#pragma unroll
            for (int i = 0; i < 4; i++)
                h[i] = *(const float4*)&hx[(size_t)b * HXLEN + (size_t)(bn + i) * UNITS + ty * 4];
#pragma unroll
            for (int j = 0; j < 4; j++) {
                float4 st;
                st.x = sigf(acc[g * 4 + 0][j] + br[j]) * ((const float*)&h[0])[j];
                st.y = sigf(acc[g * 4 + 1][j] + br[j]) * ((const float*)&h[1])[j];
                st.z = sigf(acc[g * 4 + 2][j] + br[j]) * ((const float*)&h[2])[j];
                st.w = sigf(acc[g * 4 + 3][j] + br[j]) * ((const float*)&h[3])[j];
                *(float4*)&X0b_t[(size_t)(b * CDIM + 2 + ty * 4 + j) * NNODE + bn] = st;
            }
#pragma unroll
            for (int j = 0; j < 4; j++) {
                float4 st;
                st.x = sigf(acc[g * 4 + 0][4 + j] + bu[j]);
                st.y = sigf(acc[g * 4 + 1][4 + j] + bu[j]);
                st.z = sigf(acc[g * 4 + 2][4 + j] + bu[j]);
                st.w = sigf(acc[g * 4 + 3][4 + j] + bu[j]);
                *(float4*)&u_t[(size_t)(ty * 4 + j) * ROWS + (size_t)b * NNODE + bn] = st;
            }
        }
    } else {
        float bz[4];
#pragma unroll
        for (int j = 0; j < 4; j++) bz[j] = bias[ty * 4 + j];
#pragma unroll
        for (int g = 0; g < 2; g++) {
            int bn = n0 + g * 64 + tx * 4;
            float4 uu[4];
#pragma unroll
            for (int j = 0; j < 4; j++)
                uu[j] = *(const float4*)&u_t[(size_t)(ty * 4 + j) * ROWS + (size_t)b * NNODE + bn];
#pragma unroll
            for (int i = 0; i < 4; i++) {
                float4 h = *(const float4*)&hx[(size_t)b * HXLEN + (size_t)(bn + i) * UNITS + ty * 4];
                float4 ov;
                {
                    float cc = tanhf(acc[g * 4 + i][0] + bz[0]);
                    float u0 = ((const float*)&uu[0])[i];
                    ov.x = u0 * h.x + (1.f - u0) * cc;
                }
                {
                    float cc = tanhf(acc[g * 4 + i][1] + bz[1]);
                    float u0 = ((const float*)&uu[1])[i];
                    ov.y = u0 * h.y + (1.f - u0) * cc;
                }
                {
                    float cc = tanhf(acc[g * 4 + i][2] + bz[2]);
                    float u0 = ((const float*)&uu[2])[i];
                    ov.z = u0 * h.z + (1.f - u0) * cc;
                }
                {
                    float cc = tanhf(acc[g * 4 + i][3] + bz[3]);
                    float u0 = ((const float*)&uu[3])[i];
                    ov.w = u0 * h.w + (1.f - u0) * cc;
                }
                *(float4*)&out[(size_t)b * HXLEN + (size_t)(bn + i) * UNITS + ty * 4] = ov;
            }
        }
    }
}

// ---------------------------------------------------------------------------
// launch
// ---------------------------------------------------------------------------
extern "C" void kernel_launch(void* const* d_in, const int* in_sizes, int n_in,
                              void* d_out, int out_size)
{
    const float* inputs = (const float*)d_in[0];
    const float* hx     = (const float*)d_in[1];
    const float* S0     = (const float*)d_in[2];
    const float* S1     = (const float*)d_in[3];
    const float* Wru    = (const float*)d_in[4];
    const float* bru    = (const float*)d_in[5];
    const float* Wc     = (const float*)d_in[6];
    const float* bc     = (const float*)d_in[7];
    float* out = (float*)d_out;

    float *X0A, *X0B, *X1A, *X2A, *X1B, *X2B, *U;
    cudaGetSymbolAddress((void**)&X0A, g_X0A);
    cudaGetSymbolAddress((void**)&X0B, g_X0B);
    cudaGetSymbolAddress((void**)&X1A, g_X1A);
    cudaGetSymbolAddress((void**)&X2A, g_X2A);
    cudaGetSymbolAddress((void**)&X1B, g_X1B);
    cudaGetSymbolAddress((void**)&X2B, g_X2B);
    cudaGetSymbolAddress((void**)&U,   g_U);

    dim3 gemmGrid(17, 16);
    dim3 denseGrid(16, 32);
    int buildBlocks = (int)(((size_t)NCP * NNODE + 255) / 256);

    // ---- gconv 1 (state = hx) ----
    build_x0_kernel<<<buildBlocks, 256>>>(inputs, hx, X0A, X0B);

    tc_gemm_kernel<<<gemmGrid, 256>>>(S0, X0A, nullptr, X1A, 0);
    tc_gemm_kernel<<<gemmGrid, 256>>>(S0, X1A, X0A,     X2A, 1);
    tc_gemm_kernel<<<gemmGrid, 256>>>(S1, X0A, nullptr, X1B, 0);
    tc_gemm_kernel<<<gemmGrid, 256>>>(S1, X1B, X0A,     X2B, 1);

    dense_gconv_kernel<128><<<denseGrid, 256>>>(X0A, X1A, X2A, X1B, X2B,
                                                Wru, bru, hx, U, X0B, nullptr);

    // ---- gconv 2 (state = r*hx, already in X0B) ----
    tc_gemm_kernel<<<gemmGrid, 256>>>(S0, X0B, nullptr, X1A, 0);
    tc_gemm_kernel<<<gemmGrid, 256>>>(S0, X1A, X0B,     X2A, 1);
    tc_gemm_kernel<<<gemmGrid, 256>>>(S1, X0B, nullptr, X1B, 0);
    tc_gemm_kernel<<<gemmGrid, 256>>>(S1, X1B, X0B,     X2B, 1);

    dense_gconv_kernel<64><<<denseGrid, 256>>>(X0B, X1A, X2A, X1B, X2B,
                                               Wc, bc, hx, U, nullptr, out);
}

// round 6
// speedup vs baseline: 2.9360x; 1.1796x over previous
#include <cuda_runtime.h>
#include <cstdint>
#include <math.h>

// ============================================================================
// DCGRU cell — mma.sync TF32 diffusion GEMMs (3-stage cp.async pipeline,
// one barrier per k-iter, XOR-swizzled smem) + fp32 SIMT dense gconvs.
// Static shared memory only (48 KB exactly); no dyn-smem attr, no mbarriers.
//
// All X buffers stored TRANSPOSED: Xt[col][node], col = b*66+c (padded to 2176)
// Diffusion GEMM: Yt[n][m] = sum_k S[m][k] * Xt[n][k]   (m16n8k8.row.col)
// Paired launches: blockIdx.z in {0,1} selects (S0,X0,Y0) vs (S1,X1,Y1).
// ============================================================================

#define NNODE 2048
#define BATCH 32
#define UNITS 64
#define CDIM  66
#define NC    2112            // BATCH*CDIM
#define NCP   2176            // padded to 17*128
#define ROWS  65536           // NNODE*BATCH
#define HXLEN 131072          // NNODE*UNITS

// Scratch (device globals, allocation-free)
__device__ float g_X0A[(size_t)NCP * NNODE];
__device__ float g_X0B[(size_t)NCP * NNODE];
__device__ float g_X1A[(size_t)NCP * NNODE];
__device__ float g_X2A[(size_t)NCP * NNODE];
__device__ float g_X1B[(size_t)NCP * NNODE];
__device__ float g_X2B[(size_t)NCP * NNODE];
__device__ float g_U  [(size_t)UNITS * ROWS];   // u_t[o][b*2048+n]

// ---------------------------------------------------------------------------
// helpers
// ---------------------------------------------------------------------------
__device__ __forceinline__ uint32_t smem_u32(const void* p) {
    uint32_t a;
    asm("{ .reg .u64 t; cvta.to.shared.u64 t, %1; cvt.u32.u64 %0, t; }"
        : "=r"(a) : "l"(p));
    return a;
}
__device__ __forceinline__ void cp_async16(uint32_t dst, const void* src) {
    asm volatile("cp.async.cg.shared.global [%0], [%1], 16;"
                 :: "r"(dst), "l"(src) : "memory");
}
#define CP_COMMIT() asm volatile("cp.async.commit_group;" ::: "memory")
#define CP_WAIT(n)  asm volatile("cp.async.wait_group %0;" :: "n"(n) : "memory")

// m16n8k8 tf32 mma, D+=A*B (fp32 bits as tf32 operands; HW truncates mantissa)
__device__ __forceinline__ void mma_tf32(float* c, const uint32_t* a,
                                         uint32_t b0, uint32_t b1) {
    asm volatile(
        "mma.sync.aligned.m16n8k8.row.col.f32.tf32.tf32.f32 "
        "{%0,%1,%2,%3}, {%4,%5,%6,%7}, {%8,%9}, {%0,%1,%2,%3};"
        : "+f"(c[0]), "+f"(c[1]), "+f"(c[2]), "+f"(c[3])
        : "r"(a[0]), "r"(a[1]), "r"(a[2]), "r"(a[3]), "r"(b0), "r"(b1));
}

// ---------------------------------------------------------------------------
// build_x0: fill transposed X0A (and input cols + pads of X0B)
// ---------------------------------------------------------------------------
__global__ void build_x0_kernel(const float* __restrict__ inputs,
                                const float* __restrict__ hx,
                                float* __restrict__ X0A,
                                float* __restrict__ X0B)
{
    size_t idx = (size_t)blockIdx.x * 256 + threadIdx.x;
    if (idx >= (size_t)NCP * NNODE) return;
    int col = (int)(idx >> 11);
    int n = (int)(idx & 2047);
    if (col >= NC) { X0A[idx] = 0.f; X0B[idx] = 0.f; return; }
    int b = col / CDIM;
    int c = col - b * CDIM;
    float v;
    if (c < 2) {
        v = inputs[b * (NNODE * 2) + n * 2 + c];
        X0B[idx] = v;
    } else {
        v = hx[(size_t)b * HXLEN + n * UNITS + (c - 2)];
    }
    X0A[idx] = v;
}

// ---------------------------------------------------------------------------
// tc_gemm: Y = S @ X (mode 0) / Y = 2*(S@X) - Xsub (mode 1), all transposed.
// grid (17 colTiles, 16 rowTiles, 2 pair), 256 threads, 48 KB static smem.
// 3-stage pipeline, k-tile 16, stride 16 floats with float4 XOR swizzle
// q' = q ^ ((r>>1)&3)  -> conflict-free m16n8k8 fragment LDS.
// SB (floats): A_s at s*2048, B_s at 6144+s*2048, s in {0,1,2}.
// ---------------------------------------------------------------------------
__device__ __forceinline__ void load_tile_sw(uint32_t dstB, const float* src,
                                             int k0, int tid)
{
#pragma unroll
    for (int i = 0; i < 2; i++) {
        int id = tid + i * 256;
        int r = id >> 2;              // 0..127
        int q = id & 3;               // float4 index in 16-k row
        int qs = q ^ ((r >> 1) & 3);  // swizzled slot
        cp_async16(dstB + (uint32_t)(r * 16 + qs * 4) * 4,
                   src + (size_t)r * NNODE + k0 + q * 4);
    }
}

__global__ __launch_bounds__(256)
void tc_gemm_kernel(const float* __restrict__ S0,
                    const float* __restrict__ S1,
                    const float* __restrict__ X0,
                    const float* __restrict__ X1,
                    const float* __restrict__ Xsub,
                    float* __restrict__ Y0,
                    float* __restrict__ Y1,
                    int mode)
{
    __shared__ float SB[12288];   // 48 KB
    uint32_t smB = smem_u32(SB);

    int z = blockIdx.z;
    const float* S  = z ? S1 : S0;
    const float* Xt = z ? X1 : X0;
    float*       Yt = z ? Y1 : Y0;

    int tid = threadIdx.x;
    int lane = tid & 31;
    int w = tid >> 5;
    int wm = (w & 3) * 32;     // warp m offset
    int wn = (w >> 2) * 64;    // warp n offset
    int mr = lane >> 2;        // groupID 0..7
    int kc = lane & 3;         // threadID_in_group 0..3
    int sw = (mr >> 1) & 3;    // swizzle slot xor (uniform over wm/wn/f/g)

    int rowBase = blockIdx.y * 128;   // m (output node)
    int colBase = blockIdx.x * 128;   // n (X col)

    const float* Ag = S  + (size_t)rowBase * NNODE;
    const float* Bg = Xt + (size_t)colBase * NNODE;

    float acc[2][8][4];
#pragma unroll
    for (int f = 0; f < 2; f++)
#pragma unroll
        for (int g = 0; g < 8; g++)
#pragma unroll
            for (int v = 0; v < 4; v++) acc[f][g][v] = 0.f;

    // prologue: tiles 0,1 -> stages 0,1
    load_tile_sw(smB,                  Ag, 0, tid);
    load_tile_sw(smB + 6144 * 4,       Bg, 0, tid);
    CP_COMMIT();
    load_tile_sw(smB + 2048 * 4,       Ag, 16, tid);
    load_tile_sw(smB + (6144 + 2048) * 4, Bg, 16, tid);
    CP_COMMIT();

    int s = 0;          // stage of current tile
    int sl = 2;         // stage for next issued tile
    for (int kt = 0; kt < 128; ++kt) {
        if (kt < 127) { CP_WAIT(1); } else { CP_WAIT(0); }
        __syncthreads();

        if (kt + 2 < 128) {
            load_tile_sw(smB + (uint32_t)(sl * 2048) * 4,        Ag, (kt + 2) * 16, tid);
            load_tile_sw(smB + (uint32_t)((6144 + sl * 2048)) * 4, Bg, (kt + 2) * 16, tid);
            CP_COMMIT();
        }

        const float* As = SB + s * 2048;
        const float* Bs = SB + 6144 + s * 2048;

#pragma unroll
        for (int ks = 0; ks < 2; ks++) {
            int qa0 = ((ks * 2) ^ sw) * 4 + kc;
            int qa1 = ((ks * 2 + 1) ^ sw) * 4 + kc;
            uint32_t a[2][4];
#pragma unroll
            for (int f = 0; f < 2; f++) {
                int m0 = wm + f * 16 + mr;
                a[f][0] = __float_as_uint(As[m0 * 16 + qa0]);
                a[f][1] = __float_as_uint(As[(m0 + 8) * 16 + qa0]);
                a[f][2] = __float_as_uint(As[m0 * 16 + qa1]);
                a[f][3] = __float_as_uint(As[(m0 + 8) * 16 + qa1]);
            }
#pragma unroll
            for (int g = 0; g < 8; g++) {
                int nb = wn + g * 8 + mr;
                uint32_t b0 = __float_as_uint(Bs[nb * 16 + qa0]);
                uint32_t b1 = __float_as_uint(Bs[nb * 16 + qa1]);
                mma_tf32(acc[0][g], a[0], b0, b1);
                mma_tf32(acc[1][g], a[1], b0, b1);
            }
        }

        s = (s == 2) ? 0 : s + 1;
        sl = (sl == 2) ? 0 : sl + 1;
    }
    __syncthreads();   // all compute done before epilogue reuses SB

    // ---- epilogue: transpose in 32-n chunks through SB, coalesced stores ----
    // Cs chunk: [32 n][132 m-stride]; 4224 floats, fits in SB.
    float* Cs = SB;
    for (int cc = 0; cc < 4; cc++) {
        __syncthreads();
        if ((wn == 0) == (cc < 2)) {      // wn=0 warps own chunks 0,1; wn=64 -> 2,3
            int gbase = (cc & 1) * 4;
#pragma unroll
            for (int g2 = 0; g2 < 4; g2++) {
                int g = gbase + g2;
                int jn = g * 8 - (cc & 1) * 32 + 2 * kc;   // 0..30
#pragma unroll
                for (int f = 0; f < 2; f++) {
                    int i0 = wm + f * 16 + mr;
                    Cs[jn * 132 + i0]           = acc[f][g][0];
                    Cs[(jn + 1) * 132 + i0]     = acc[f][g][1];
                    Cs[jn * 132 + i0 + 8]       = acc[f][g][2];
                    Cs[(jn + 1) * 132 + i0 + 8] = acc[f][g][3];
                }
            }
        }
        __syncthreads();
#pragma unroll
        for (int i = 0; i < 4; i++) {
            int u = tid + i * 256;
            int n = u >> 5;            // 0..31
            int mq = u & 31;           // float4 index within 128 m
            float4 v = *(const float4*)&Cs[n * 132 + mq * 4];
            size_t off = (size_t)(colBase + cc * 32 + n) * NNODE + rowBase + mq * 4;
            if (mode) {
                float4 xs = *(const float4*)&Xsub[off];
                v.x = 2.f * v.x - xs.x;
                v.y = 2.f * v.y - xs.y;
                v.z = 2.f * v.z - xs.z;
                v.w = 2.f * v.w - xs.w;
            }
            *(float4*)&Yt[off] = v;
        }
    }
}

// ---------------------------------------------------------------------------
// dense_gconv<OUT>: Z[(b,n)][o] = bias[o] + sum_m sum_c Xt_m[b*66+c][n]*W[(c*5+m)*OUT+o]
// grid (16 nTiles, 32 b), 256 threads. tx -> n (rows), ty -> o (cols).
// OUT=128: sigmoid; o<64 -> r*hx into X0Bt, o>=64 -> u into u_t
// OUT=64 : tanh; final new_state into out (original layout)
// ---------------------------------------------------------------------------
__device__ __forceinline__ float sigf(float x) { return 1.f / (1.f + expf(-x)); }

template <int OUT>
__global__ __launch_bounds__(256)
void dense_gconv_kernel(const float* __restrict__ Xm0,
                        const float* __restrict__ Xm1,
                        const float* __restrict__ Xm2,
                        const float* __restrict__ Xm3,
                        const float* __restrict__ Xm4,
                        const float* __restrict__ W,
                        const float* __restrict__ bias,
                        const float* __restrict__ hx,
                        float* __restrict__ u_t,
                        float* __restrict__ X0b_t,
                        float* __restrict__ out)
{
    constexpr int JF = (OUT == 128) ? 8 : 4;

    __shared__ float Xs[33][128];
    __shared__ float Ws[33][OUT];

    int tid = threadIdx.x;
    int tx = tid & 15;    // n groups
    int ty = tid >> 4;    // o groups
    int n0 = blockIdx.x * 128;
    int b  = blockIdx.y;

    float acc[8][JF];
#pragma unroll
    for (int i = 0; i < 8; i++)
#pragma unroll
        for (int j = 0; j < JF; j++) acc[i][j] = 0.f;

    const float* Xp[5] = {Xm0, Xm1, Xm2, Xm3, Xm4};

#pragma unroll
    for (int mm = 0; mm < 5; mm++) {
        const float* Xb = Xp[mm];
        for (int half = 0; half < 2; half++) {
            int c0 = half * 33;
            __syncthreads();
            for (int i4 = tid; i4 < 33 * 32; i4 += 256) {
                int c = i4 >> 5;
                int n4 = i4 & 31;
                *(float4*)&Xs[c][n4 * 4] =
                    *(const float4*)&Xb[(size_t)(b * CDIM + c0 + c) * NNODE + n0 + n4 * 4];
            }
            for (int i4 = tid; i4 < 33 * (OUT / 4); i4 += 256) {
                int c = i4 / (OUT / 4);
                int o4 = i4 - c * (OUT / 4);
                *(float4*)&Ws[c][o4 * 4] =
                    *(const float4*)&W[(size_t)((c0 + c) * 5 + mm) * OUT + o4 * 4];
            }
            __syncthreads();

            for (int c = 0; c < 33; c++) {
                float4 a0 = *(const float4*)&Xs[c][tx * 4];
                float4 a1 = *(const float4*)&Xs[c][64 + tx * 4];
                float a[8] = {a0.x, a0.y, a0.z, a0.w, a1.x, a1.y, a1.z, a1.w};
                float4 w0 = *(const float4*)&Ws[c][ty * 4];
                float bb[JF];
                bb[0] = w0.x; bb[1] = w0.y; bb[2] = w0.z; bb[3] = w0.w;
                if (OUT == 128) {
                    float4 w1 = *(const float4*)&Ws[c][64 + ty * 4];
                    bb[4] = w1.x; bb[5] = w1.y; bb[6] = w1.z; bb[7] = w1.w;
                }
#pragma unroll
                for (int i = 0; i < 8; i++)
#pragma unroll
                    for (int j = 0; j < JF; j++)
                        acc[i][j] = fmaf(a[i], bb[j], acc[i][j]);
            }
        }
    }

    // ---- epilogue ----
    if (OUT == 128) {
        float br[4], bu[4];
#pragma unroll
        for (int j = 0; j < 4; j++) { br[j] = bias[ty * 4 + j]; bu[j] = bias[64 + ty * 4 + j]; }
#pragma unroll
        for (int g = 0; g < 2; g++) {
            int bn = n0 + g * 64 + tx * 4;
            float4 h[4];
#pragma unroll
            for (int i = 0; i < 4; i++)
                h[i] = *(const float4*)&hx[(size_t)b * HXLEN + (size_t)(bn + i) * UNITS + ty * 4];
#pragma unroll
            for (int j = 0; j < 4; j++) {
                float4 st;
                st.x = sigf(acc[g * 4 + 0][j] + br[j]) * ((const float*)&h[0])[j];
                st.y = sigf(acc[g * 4 + 1][j] + br[j]) * ((const float*)&h[1])[j];
                st.z = sigf(acc[g * 4 + 2][j] + br[j]) * ((const float*)&h[2])[j];
                st.w = sigf(acc[g * 4 + 3][j] + br[j]) * ((const float*)&h[3])[j];
                *(float4*)&X0b_t[(size_t)(b * CDIM + 2 + ty * 4 + j) * NNODE + bn] = st;
            }
#pragma unroll
            for (int j = 0; j < 4; j++) {
                float4 st;
                st.x = sigf(acc[g * 4 + 0][4 + j] + bu[j]);
                st.y = sigf(acc[g * 4 + 1][4 + j] + bu[j]);
                st.z = sigf(acc[g * 4 + 2][4 + j] + bu[j]);
                st.w = sigf(acc[g * 4 + 3][4 + j] + bu[j]);
                *(float4*)&u_t[(size_t)(ty * 4 + j) * ROWS + (size_t)b * NNODE + bn] = st;
            }
        }
    } else {
        float bz[4];
#pragma unroll
        for (int j = 0; j < 4; j++) bz[j] = bias[ty * 4 + j];
#pragma unroll
        for (int g = 0; g < 2; g++) {
            int bn = n0 + g * 64 + tx * 4;
            float4 uu[4];
#pragma unroll
            for (int j = 0; j < 4; j++)
                uu[j] = *(const float4*)&u_t[(size_t)(ty * 4 + j) * ROWS + (size_t)b * NNODE + bn];
#pragma unroll
            for (int i = 0; i < 4; i++) {
                float4 h = *(const float4*)&hx[(size_t)b * HXLEN + (size_t)(bn + i) * UNITS + ty * 4];
                float4 ov;
                {
                    float cc = tanhf(acc[g * 4 + i][0] + bz[0]);
                    float u0 = ((const float*)&uu[0])[i];
                    ov.x = u0 * h.x + (1.f - u0) * cc;
                }
                {
                    float cc = tanhf(acc[g * 4 + i][1] + bz[1]);
                    float u0 = ((const float*)&uu[1])[i];
                    ov.y = u0 * h.y + (1.f - u0) * cc;
                }
                {
                    float cc = tanhf(acc[g * 4 + i][2] + bz[2]);
                    float u0 = ((const float*)&uu[2])[i];
                    ov.z = u0 * h.z + (1.f - u0) * cc;
                }
                {
                    float cc = tanhf(acc[g * 4 + i][3] + bz[3]);
                    float u0 = ((const float*)&uu[3])[i];
                    ov.w = u0 * h.w + (1.f - u0) * cc;
                }
                *(float4*)&out[(size_t)b * HXLEN + (size_t)(bn + i) * UNITS + ty * 4] = ov;
            }
        }
    }
}

// ---------------------------------------------------------------------------
// launch
// ---------------------------------------------------------------------------
extern "C" void kernel_launch(void* const* d_in, const int* in_sizes, int n_in,
                              void* d_out, int out_size)
{
    const float* inputs = (const float*)d_in[0];
    const float* hx     = (const float*)d_in[1];
    const float* S0     = (const float*)d_in[2];
    const float* S1     = (const float*)d_in[3];
    const float* Wru    = (const float*)d_in[4];
    const float* bru    = (const float*)d_in[5];
    const float* Wc     = (const float*)d_in[6];
    const float* bc     = (const float*)d_in[7];
    float* out = (float*)d_out;

    float *X0A, *X0B, *X1A, *X2A, *X1B, *X2B, *U;
    cudaGetSymbolAddress((void**)&X0A, g_X0A);
    cudaGetSymbolAddress((void**)&X0B, g_X0B);
    cudaGetSymbolAddress((void**)&X1A, g_X1A);
    cudaGetSymbolAddress((void**)&X2A, g_X2A);
    cudaGetSymbolAddress((void**)&X1B, g_X1B);
    cudaGetSymbolAddress((void**)&X2B, g_X2B);
    cudaGetSymbolAddress((void**)&U,   g_U);

    dim3 gemmGrid(17, 16, 2);
    dim3 denseGrid(16, 32);
    int buildBlocks = (int)(((size_t)NCP * NNODE + 255) / 256);

    // ---- gconv 1 (state = hx) ----
    build_x0_kernel<<<buildBlocks, 256>>>(inputs, hx, X0A, X0B);

    tc_gemm_kernel<<<gemmGrid, 256>>>(S0, S1, X0A, X0A, nullptr, X1A, X1B, 0);
    tc_gemm_kernel<<<gemmGrid, 256>>>(S0, S1, X1A, X1B, X0A,     X2A, X2B, 1);

    dense_gconv_kernel<128><<<denseGrid, 256>>>(X0A, X1A, X2A, X1B, X2B,
                                                Wru, bru, hx, U, X0B, nullptr);

    // ---- gconv 2 (state = r*hx, already in X0B) ----
    tc_gemm_kernel<<<gemmGrid, 256>>>(S0, S1, X0B, X0B, nullptr, X1A, X1B, 0);
    tc_gemm_kernel<<<gemmGrid, 256>>>(S0, S1, X1A, X1B, X0B,     X2A, X2B, 1);

    dense_gconv_kernel<64><<<denseGrid, 256>>>(X0B, X1A, X2A, X1B, X2B,
                                               Wc, bc, hx, U, nullptr, out);
}